// round 3
// baseline (speedup 1.0000x reference)
#include <cuda_runtime.h>
#include <cuda_pipeline.h>
#include <cstdint>

#define N_NODES 32768
#define EMB 128
#define N_CODES 4096
#define NG 512

// output layout: c_logit[512], c_graph[512*128], s_graph[512*128],
// loss_c, loss_s, c_node[32768*128], s_node[32768*128]
#define OFF_LOGIT 0
#define OFF_CG    512
#define OFF_SG    (512 + 65536)
#define OFF_LC    (512 + 2 * 65536)
#define OFF_LS    (OFF_LC + 1)
#define OFF_CN    (OFF_LS + 1)
#define OFF_SN    (OFF_CN + N_NODES * EMB)

// device scratch (no allocations allowed)
__device__ float g_CT[128 * 8192];              // transposed concat codebook [k][n]
__device__ float g_halfc2[8192];                // 0.5*|c_n|^2
__device__ unsigned long long g_keyc[N_NODES];  // packed (dist,idx) argmin keys
__device__ unsigned long long g_keys[N_NODES];
__device__ int g_counts[NG];
__device__ double g_loss[2];

__device__ __forceinline__ void ffma2(unsigned long long& d, unsigned long long a,
                                      unsigned long long b) {
    asm volatile("fma.rn.f32x2 %0, %1, %2, %0;" : "+l"(d) : "l"(a), "l"(b));
}
__device__ __forceinline__ unsigned long long packf2(float a) {
    unsigned long long r; asm("mov.b64 %0, {%1, %1};" : "=l"(r) : "f"(a)); return r;
}
__device__ __forceinline__ float2 unpackf2(unsigned long long v) {
    float2 p; asm("mov.b64 {%0, %1}, %2;" : "=f"(p.x), "=f"(p.y) : "l"(v)); return p;
}
__device__ __forceinline__ unsigned int fkey(float f) {
    unsigned u = __float_as_uint(f);
    return (u & 0x80000000u) ? ~u : (u | 0x80000000u);
}

// ---------- init ----------
__global__ void init_kernel(float* __restrict__ out) {
    int i = blockIdx.x * blockDim.x + threadIdx.x;  // 65536 threads
    if (i < N_NODES) { g_keyc[i] = ~0ULL; g_keys[i] = ~0ULL; }
    if (i < NG) g_counts[i] = 0;
    if (i < 2) g_loss[i] = 0.0;
    out[OFF_CG + 2 * i] = 0.f;
    out[OFF_CG + 2 * i + 1] = 0.f;
}

// ---------- transpose concat codebook into g_CT[k][n] ----------
__global__ void transpose_kernel(const float* __restrict__ cbc, const float* __restrict__ cbs) {
    __shared__ float t[32][33];
    int bx = blockIdx.x, by = blockIdx.y;
    int tx = threadIdx.x, ty = threadIdx.y;  // (32,8)
    for (int yy = ty; yy < 32; yy += 8) {
        int n = bx * 32 + yy, k = by * 32 + tx;
        t[yy][tx] = (n < N_CODES) ? cbc[(size_t)n * EMB + k]
                                  : cbs[(size_t)(n - N_CODES) * EMB + k];
    }
    __syncthreads();
    for (int yy = ty; yy < 32; yy += 8) {
        int k = by * 32 + yy, n = bx * 32 + tx;
        g_CT[(size_t)k * 8192 + n] = t[tx][yy];
    }
}

// ---------- 0.5*|c|^2 ----------
__global__ void halfc2_kernel(const float* __restrict__ cbc, const float* __restrict__ cbs) {
    int w = blockIdx.x * 8 + (threadIdx.x >> 5);
    int lane = threadIdx.x & 31;
    const float* row = (w < N_CODES) ? (cbc + (size_t)w * EMB)
                                     : (cbs + (size_t)(w - N_CODES) * EMB);
    float4 v = ((const float4*)row)[lane];
    float s = v.x * v.x + v.y * v.y + v.z * v.z + v.w * v.w;
    for (int o = 16; o; o >>= 1) s += __shfl_xor_sync(0xffffffffu, s, o);
    if (lane == 0) g_halfc2[w] = 0.5f * s;
}

// ---------- main GEMM + argmin ----------
// grid 1024: mb = bid>>2 (128 nodes), nr = bid&3 (2048 codes = 16 chunks of 128)
#define SMEM_BYTES (65536 + 131072 + 1024 + 512 + 1024)

__global__ void __launch_bounds__(128, 1)
gemm_argmin_kernel(const float* __restrict__ nodef, const float* __restrict__ score) {
    extern __shared__ char smem[];
    float* As = (float*)smem;                       // [k][m] 64KB
    float* Bs = (float*)(smem + 65536);             // 2 x [k][128n] 128KB
    float* c2s = (float*)(smem + 65536 + 131072);   // 2 x 128
    float* gbuf = c2s + 256;                        // 128
    unsigned long long* bestk = (unsigned long long*)(gbuf + 128);  // 128

    const int tid = threadIdx.x;
    const int tx = tid & 15, ty = tid >> 4;
    const int m0 = ty * 16;
    const int mb = blockIdx.x >> 2;
    const int nr = blockIdx.x & 3;
    const int mbase = mb * 128;
    const int nbase = nr * 2048;
    const int cb = nbase >> 12;  // 0 = codebook_c half, 1 = codebook_s half

    // prologue: async-copy B chunk 0 + its half|c|^2 slice
    for (int s = 0; s < 32; s++) {
        int kk = (tid >> 5) + 4 * s, c4 = tid & 31;
        __pipeline_memcpy_async(Bs + kk * 128 + c4 * 4,
                                g_CT + (size_t)kk * 8192 + nbase + c4 * 4, 16);
    }
    if (tid < 32) __pipeline_memcpy_async(c2s + tid * 4, g_halfc2 + nbase + tid * 4, 16);
    __pipeline_commit();

    bestk[tid] = ~0ULL;
    {
        float s = score[mbase + tid];
        gbuf[tid] = cb ? (1.0f - 0.5f * s) : (0.5f + 0.5f * s);
    }
    // A load, transposed into [k][m]
    {
        const float4* Ar = (const float4*)(nodef + (size_t)(mbase + tid) * EMB);
        for (int c4 = 0; c4 < 32; c4++) {
            float4 v = Ar[c4];
            As[(c4 * 4 + 0) * 128 + tid] = v.x;
            As[(c4 * 4 + 1) * 128 + tid] = v.y;
            As[(c4 * 4 + 2) * 128 + tid] = v.z;
            As[(c4 * 4 + 3) * 128 + tid] = v.w;
        }
    }
    __syncthreads();

    unsigned long long acc[16][4];
    float4 af[2][4];
    unsigned long long bf[2][4];

    for (int ci = 0; ci < 16; ci++) {
        float* Bcur = Bs + (ci & 1) * 16384;
        const float* c2cur = c2s + (ci & 1) * 128;
        __pipeline_wait_prior(0);
        __syncthreads();
        if (ci + 1 < 16) {
            float* dst = Bs + ((ci + 1) & 1) * 16384;
            int nco = nbase + (ci + 1) * 128;
            for (int s = 0; s < 32; s++) {
                int kk = (tid >> 5) + 4 * s, c4 = tid & 31;
                __pipeline_memcpy_async(dst + kk * 128 + c4 * 4,
                                        g_CT + (size_t)kk * 8192 + nco + c4 * 4, 16);
            }
            if (tid < 32)
                __pipeline_memcpy_async(c2s + ((ci + 1) & 1) * 128 + tid * 4,
                                        g_halfc2 + nco + tid * 4, 16);
            __pipeline_commit();
        }

#pragma unroll
        for (int i = 0; i < 16; i++)
#pragma unroll
            for (int j = 0; j < 4; j++) acc[i][j] = 0ULL;

        {   // frag k=0
            const float4* Arow = (const float4*)(As + m0);
#pragma unroll
            for (int q = 0; q < 4; q++) af[0][q] = Arow[q];
            const unsigned long long* Brow = (const unsigned long long*)Bcur;
#pragma unroll
            for (int j = 0; j < 4; j++) bf[0][j] = Brow[tx + 16 * j];
        }

#pragma unroll 2
        for (int k = 0; k < 128; k++) {
            const int cur = k & 1, nxt = cur ^ 1;
            if (k < 127) {
                const float4* Arow = (const float4*)(As + (k + 1) * 128 + m0);
#pragma unroll
                for (int q = 0; q < 4; q++) af[nxt][q] = Arow[q];
                const unsigned long long* Brow =
                    (const unsigned long long*)(Bcur + (k + 1) * 128);
#pragma unroll
                for (int j = 0; j < 4; j++) bf[nxt][j] = Brow[tx + 16 * j];
            }
#pragma unroll
            for (int q = 0; q < 4; q++) {
                float4 a4 = af[cur][q];
                unsigned long long am;
                am = packf2(a4.x);
                ffma2(acc[q * 4 + 0][0], am, bf[cur][0]); ffma2(acc[q * 4 + 0][1], am, bf[cur][1]);
                ffma2(acc[q * 4 + 0][2], am, bf[cur][2]); ffma2(acc[q * 4 + 0][3], am, bf[cur][3]);
                am = packf2(a4.y);
                ffma2(acc[q * 4 + 1][0], am, bf[cur][0]); ffma2(acc[q * 4 + 1][1], am, bf[cur][1]);
                ffma2(acc[q * 4 + 1][2], am, bf[cur][2]); ffma2(acc[q * 4 + 1][3], am, bf[cur][3]);
                am = packf2(a4.z);
                ffma2(acc[q * 4 + 2][0], am, bf[cur][0]); ffma2(acc[q * 4 + 2][1], am, bf[cur][1]);
                ffma2(acc[q * 4 + 2][2], am, bf[cur][2]); ffma2(acc[q * 4 + 2][3], am, bf[cur][3]);
                am = packf2(a4.w);
                ffma2(acc[q * 4 + 3][0], am, bf[cur][0]); ffma2(acc[q * 4 + 3][1], am, bf[cur][1]);
                ffma2(acc[q * 4 + 3][2], am, bf[cur][2]); ffma2(acc[q * 4 + 3][3], am, bf[cur][3]);
            }
        }

        // epilogue: running argmin of (0.5|c|^2 - g*<x,c>)
        int cbBaseIdx = (nbase & 4095) + ci * 128;
#pragma unroll
        for (int mm = 0; mm < 16; mm++) {
            float g = gbuf[m0 + mm];
            float best = __int_as_float(0x7f800000);
            int bi = 0;
#pragma unroll
            for (int j = 0; j < 4; j++) {
                float2 p = unpackf2(acc[mm][j]);
                int nl = 2 * tx + 32 * j;
                float v0 = fmaf(-g, p.x, c2cur[nl]);
                float v1 = fmaf(-g, p.y, c2cur[nl + 1]);
                if (v0 < best) { best = v0; bi = nl; }
                if (v1 < best) { best = v1; bi = nl + 1; }
            }
            unsigned long long key =
                ((unsigned long long)fkey(best) << 32) | (unsigned)(cbBaseIdx + bi);
#pragma unroll
            for (int o = 8; o; o >>= 1) {
                unsigned long long other = __shfl_xor_sync(0xffffffffu, key, o, 16);
                if (other < key) key = other;
            }
            if (tx == 0 && key < bestk[m0 + mm]) bestk[m0 + mm] = key;
        }
    }
    __syncthreads();
    atomicMin((cb ? g_keys : g_keyc) + mbase + tid, bestk[tid]);
}

// ---------- per-node outputs + segment sums + commit losses ----------
__global__ void __launch_bounds__(128)
node_kernel(const float* __restrict__ nodef, const float* __restrict__ score,
            const int* __restrict__ batch,
            const float* __restrict__ cbc, const float* __restrict__ cbs,
            float* __restrict__ out) {
    __shared__ float s_sh[64];
    __shared__ int b_sh[64], ic_sh[64], is_sh[64];
    __shared__ double lred[8];
    const int tid = threadIdx.x;
    const int n0 = blockIdx.x * 64;
    if (tid < 64) {
        int n = n0 + tid;
        s_sh[tid] = score[n];
        b_sh[tid] = batch[n];
        ic_sh[tid] = (int)(g_keyc[n] & 0xffffffffULL);
        is_sh[tid] = (int)(g_keys[n] & 0xffffffffULL);
    }
    __syncthreads();
    float* csum = out + OFF_CG;
    float* ssum = out + OFF_SG;
    float* cn = out + OFF_CN;
    float* sn = out + OFF_SN;
    const int d = tid;
    float cacc = 0.f, sacc = 0.f;
    double lc = 0.0, ls = 0.0;
    int curg = b_sh[0], runlen = 0;
    for (int i = 0; i < 64; i++) {
        int n = n0 + i;
        int gidx = b_sh[i];
        if (gidx != curg) {
            atomicAdd(&csum[curg * EMB + d], cacc);
            atomicAdd(&ssum[curg * EMB + d], sacc);
            if (d == 0) atomicAdd(&g_counts[curg], runlen);
            cacc = 0.f; sacc = 0.f; runlen = 0; curg = gidx;
        }
        float x = nodef[(size_t)n * EMB + d];
        float s = s_sh[i];
        float qc = cbc[(size_t)ic_sh[i] * EMB + d];
        float qs = cbs[(size_t)is_sh[i] * EMB + d];
        float cv = x * s + qc;
        float sv = x * (1.f - s) + qs;
        cn[(size_t)n * EMB + d] = cv;
        sn[(size_t)n * EMB + d] = sv;
        float dc = qc - (0.5f + 0.5f * s) * x;
        float ds = qs - (1.0f - 0.5f * s) * x;
        lc += (double)(dc * dc);
        ls += (double)(ds * ds);
        cacc += cv; sacc += sv; runlen++;
    }
    atomicAdd(&csum[curg * EMB + d], cacc);
    atomicAdd(&ssum[curg * EMB + d], sacc);
    if (d == 0) atomicAdd(&g_counts[curg], runlen);
    for (int o = 16; o; o >>= 1) {
        lc += __shfl_xor_sync(0xffffffffu, lc, o);
        ls += __shfl_xor_sync(0xffffffffu, ls, o);
    }
    int w = tid >> 5, lane = tid & 31;
    if (lane == 0) { lred[w] = lc; lred[4 + w] = ls; }
    __syncthreads();
    if (tid == 0) {
        atomicAdd(&g_loss[0], lred[0] + lred[1] + lred[2] + lred[3]);
        atomicAdd(&g_loss[1], lred[4] + lred[5] + lred[6] + lred[7]);
    }
}

// ---------- finalize means + losses ----------
__global__ void finalize_kernel(float* __restrict__ out) {
    int g = blockIdx.x, d = threadIdx.x;
    float cnt = fmaxf((float)g_counts[g], 1.0f);
    out[OFF_CG + g * EMB + d] /= cnt;
    out[OFF_SG + g * EMB + d] /= cnt;
    if (g == 0 && d == 0) {
        out[OFF_LC] = (float)(g_loss[0] / ((double)N_NODES * (double)EMB));
        out[OFF_LS] = (float)(g_loss[1] / ((double)N_NODES * (double)EMB));
    }
}

// ---------- classifier head ----------
__global__ void __launch_bounds__(256)
classifier_kernel(const float* __restrict__ w1, const float* __restrict__ b1,
                  const float* __restrict__ gamma, const float* __restrict__ beta,
                  const float* __restrict__ rmean, const float* __restrict__ rvar,
                  const float* __restrict__ w2, const float* __restrict__ b2,
                  float* __restrict__ out) {
    __shared__ float cg_s[128];
    __shared__ float red[256];
    int g = blockIdx.x, j = threadIdx.x;
    if (j < 128) cg_s[j] = out[OFF_CG + g * EMB + j];
    __syncthreads();
    float acc = 0.f;
#pragma unroll 8
    for (int k = 0; k < 128; k++) acc = fmaf(cg_s[k], w1[k * 256 + j], acc);
    float h = acc + b1[j];
    h = (h - rmean[j]) * rsqrtf(rvar[j] + 1e-5f) * gamma[j] + beta[j];
    h = fmaxf(h, 0.f);
    red[j] = h * w2[j];
    __syncthreads();
    for (int o = 128; o; o >>= 1) {
        if (j < o) red[j] += red[j + o];
        __syncthreads();
    }
    if (j == 0) out[OFF_LOGIT + g] = red[0] + b2[0];
}

extern "C" void kernel_launch(void* const* d_in, const int* in_sizes, int n_in,
                              void* d_out, int out_size) {
    (void)in_sizes; (void)n_in; (void)out_size;
    const float* nodef = (const float*)d_in[0];
    const float* score = (const float*)d_in[1];
    const int* batch = (const int*)d_in[2];
    const float* cbc = (const float*)d_in[3];
    const float* cbs = (const float*)d_in[4];
    const float* w1 = (const float*)d_in[5];
    const float* b1 = (const float*)d_in[6];
    const float* gamma = (const float*)d_in[7];
    const float* beta = (const float*)d_in[8];
    const float* rmean = (const float*)d_in[9];
    const float* rvar = (const float*)d_in[10];
    const float* w2 = (const float*)d_in[11];
    const float* b2 = (const float*)d_in[12];
    float* out = (float*)d_out;

    cudaFuncSetAttribute(gemm_argmin_kernel,
                         cudaFuncAttributeMaxDynamicSharedMemorySize, SMEM_BYTES);

    init_kernel<<<256, 256>>>(out);
    transpose_kernel<<<dim3(256, 4), dim3(32, 8)>>>(cbc, cbs);
    halfc2_kernel<<<1024, 256>>>(cbc, cbs);
    gemm_argmin_kernel<<<1024, 128, SMEM_BYTES>>>(nodef, score);
    node_kernel<<<512, 128>>>(nodef, score, batch, cbc, cbs, out);
    finalize_kernel<<<NG, 128>>>(out);
    classifier_kernel<<<NG, 256>>>(w1, b1, gamma, beta, rmean, rvar, w2, b2, out);
}